// round 13
// baseline (speedup 1.0000x reference)
#include <cuda_runtime.h>
#include <cuda_fp16.h>
#include <cstdint>
#include <cstddef>

#define NN   50000
#define EE   800000
#define DIN  128
#define DH   256
#define NBLK ((NN + 255) / 256)   // 196 scan blocks

// ---------------- scratch (device globals; no allocation allowed) ------------
__device__ float  g_dinv[NN];             // weighted in-degree -> rsqrt in place
__device__ int    g_count[NN];            // per-dst edge count
__device__ int    g_rowstart[NN + 1];     // CSR offsets
__device__ uint2  g_stage[EE];            // (src | dst<<16, rank)
__device__ int2   g_csr[EE];              // packed (src, w*dinv[s] as bits)
__device__ __half g_xh[NN * DIN];         // x in fp16
__device__ __half g_a1h[NN * DIN];        // A @ x in fp16 (GEMM input)
__device__ __half g_ph[NN * DIN];         // fused-GEMM output in fp16
__device__ __half g_w1h[DH * DIN];        // W1 fp16
__device__ __half g_w2h[DIN * DH];        // W2 fp16
__device__ int    g_is64;
__device__ int    g_ticket;                        // lookback ticket
__device__ unsigned long long g_state[NBLK];       // value<<2 | flag

// ---------------- zero scratch + dtype detect (edge-chain head) --------------
__global__ void zero_kernel(const int* __restrict__ raw,
                            float* __restrict__ deg,
                            int* __restrict__ cnt) {
    const int gtid   = blockIdx.x * blockDim.x + threadIdx.x;
    const int stride = gridDim.x * blockDim.x;
    for (int i = gtid; i < NN; i += stride) { deg[i] = 0.f; cnt[i] = 0; }
    for (int i = gtid; i < NBLK; i += stride) g_state[i] = 0ull;
    if (gtid == 0) g_ticket = 0;
    if (blockIdx.x == 0) {
        int odd = (threadIdx.x < 128) ? raw[2 * threadIdx.x + 1] : 0;
        int any = __syncthreads_or(odd != 0);
        if (threadIdx.x == 0) g_is64 = any ? 0 : 1;
    }
}

// ---------------- fp16 conversions (side-stream branch) ----------------------
__global__ void conv_kernel(const float* __restrict__ x,
                            const float* __restrict__ W1,
                            const float* __restrict__ W2) {
    const int gtid   = blockIdx.x * blockDim.x + threadIdx.x;
    const int stride = gridDim.x * blockDim.x;

    const int pairs = NN * DIN / 2;
    const float2* xin = (const float2*)x;
    __half2* xo = (__half2*)g_xh;
    for (int i = gtid; i < pairs; i += stride) {
        float2 v = xin[i];
        xo[i] = __floats2half2_rn(v.x, v.y);
    }
    const int wp = DH * DIN / 2;
    const float2* w1in = (const float2*)W1;
    const float2* w2in = (const float2*)W2;
    __half2* w1o = (__half2*)g_w1h;
    __half2* w2o = (__half2*)g_w2h;
    for (int i = gtid; i < wp; i += stride) {
        float2 a = w1in[i];
        float2 b = w2in[i];
        w1o[i] = __floats2half2_rn(a.x, a.y);
        w2o[i] = __floats2half2_rn(b.x, b.y);
    }
}

// ---------------- index decode helper ----------------------------------------
__device__ __forceinline__ void decode_edge(const void* raw, int e, int i,
                                            int& s, int& d) {
    if (g_is64) {
        const long long* p = (const long long*)raw;
        s = (int)p[i];
        d = (int)p[(size_t)e + i];
    } else {
        const int* p = (const int*)raw;
        s = p[i];
        d = p[e + i];
    }
}

// ------- degree/counts + stage (src,dst,rank); 4 edges per thread ------------
__global__ void convert_deg_kernel(const void* __restrict__ raw,
                                   const float* __restrict__ w,
                                   float* __restrict__ deg,
                                   int* __restrict__ cnt,
                                   uint2* __restrict__ stage, int e) {
    int base = (blockIdx.x * blockDim.x + threadIdx.x) * 4;
    if (base >= e) return;
    int cntk = min(4, e - base);
#pragma unroll
    for (int k = 0; k < 4; k++) {
        if (k >= cntk) break;
        int s, d;
        decode_edge(raw, e, base + k, s, d);
        float wv = w[base + k];
        atomicAdd(&deg[d], wv);
        int r = atomicAdd(&cnt[d], 1);
        stage[base + k] =
            make_uint2((unsigned)s | ((unsigned)d << 16), (unsigned)r);
    }
}

// ---------------- single-pass lookback scan (+dinv fused) --------------------
__device__ __forceinline__ int block_scan_incl(int v) {
    const int lane = threadIdx.x & 31;
    const int warp = threadIdx.x >> 5;
    int s = v;
#pragma unroll
    for (int o = 1; o < 32; o <<= 1) {
        int t = __shfl_up_sync(0xFFFFFFFFu, s, o);
        if (lane >= o) s += t;
    }
    __shared__ int wsum[8];
    if (lane == 31) wsum[warp] = s;
    __syncthreads();
    if (warp == 0 && lane < 8) {
        int ws = wsum[lane];
#pragma unroll
        for (int o = 1; o < 8; o <<= 1) {
            int t = __shfl_up_sync(0xFFu, ws, o);
            if (lane >= o) ws += t;
        }
        wsum[lane] = ws;
    }
    __syncthreads();
    return s + (warp > 0 ? wsum[warp - 1] : 0);
}

__global__ void scan_lookback_kernel(const int* __restrict__ cnt,
                                     float* __restrict__ deg,   // -> dinv
                                     int* __restrict__ rowstart, int n) {
    __shared__ int s_bid, s_total, s_excl;
    if (threadIdx.x == 0) s_bid = atomicAdd(&g_ticket, 1);
    __syncthreads();
    const int bid = s_bid;
    const int idx = bid * 256 + threadIdx.x;

    int v = (idx < n) ? cnt[idx] : 0;
    int incl = block_scan_incl(v);
    if (threadIdx.x == 255) s_total = incl;
    __syncthreads();

    if (threadIdx.x == 0) {
        volatile unsigned long long* st = g_state;
        unsigned long long pkt =
            ((unsigned long long)s_total << 2) | (bid == 0 ? 2ull : 1ull);
        __threadfence();
        st[bid] = pkt;
        int excl = 0;
        if (bid > 0) {
            int j = bid - 1;
            while (true) {
                unsigned long long sv = st[j];
                unsigned f = (unsigned)(sv & 3ull);
                if (f == 0) continue;
                excl += (int)(sv >> 2);
                if (f == 2) break;
                j--;
            }
            unsigned long long pkt2 =
                ((unsigned long long)(excl + s_total) << 2) | 2ull;
            __threadfence();
            st[bid] = pkt2;
        }
        s_excl = excl;
    }
    __syncthreads();

    const int base = s_excl;
    if (idx < n) {
        rowstart[idx] = base + incl - v;
        deg[idx] = rsqrtf(deg[idx] + 1.0f);   // dinv fused (+1 = self-loop)
    }
    if (bid == (n + 255) / 256 - 1 && threadIdx.x == 255)
        rowstart[n] = base + s_total;
}

// --------- CSR fill: pos = rowstart[d] + rank; store (s, w*dinv[s]) ----------
// 4 edges per thread, batched loads for MLP.
__global__ void csr_fill_kernel(const uint2* __restrict__ stage,
                                const float* __restrict__ w,
                                const float* __restrict__ dinv,
                                const int* __restrict__ rowstart,
                                int2* __restrict__ csr, int e) {
    int base = (blockIdx.x * blockDim.x + threadIdx.x) * 4;
    if (base >= e) return;
    int cntk = min(4, e - base);

    uint2 st[4];
    float wv[4];
#pragma unroll
    for (int k = 0; k < 4; k++) {
        if (k < cntk) { st[k] = stage[base + k]; wv[k] = w[base + k]; }
        else          { st[k] = make_uint2(0u, 0u); wv[k] = 0.f; }
    }
    int   s[4], d[4];
    float ds[4];
    int   rs[4];
#pragma unroll
    for (int k = 0; k < 4; k++) {
        s[k] = (int)(st[k].x & 0xFFFFu);
        d[k] = (int)(st[k].x >> 16);
    }
#pragma unroll
    for (int k = 0; k < 4; k++) ds[k] = dinv[s[k]];
#pragma unroll
    for (int k = 0; k < 4; k++) rs[k] = rowstart[d[k]];
#pragma unroll
    for (int k = 0; k < 4; k++) {
        if (k < cntk)
            csr[rs[k] + (int)st[k].y] =
                make_int2(s[k], __float_as_int(wv[k] * ds[k]));
    }
}

// ---------------- CSR gather over fp16 features, fp32 accumulate -------------
__device__ __forceinline__ float4 h4_to_f4(uint2 u) {
    __half2 a = *(__half2*)&u.x;
    __half2 b = *(__half2*)&u.y;
    float2 fa = __half22float2(a);
    float2 fb = __half22float2(b);
    return make_float4(fa.x, fa.y, fb.x, fb.y);
}

// DO_LN=0: write fp16 (outb = __half*). DO_LN=1: LN, write fp32 (outb = float*)
template <int DO_LN>
__global__ __launch_bounds__(256)
void gather_kernel(const int* __restrict__ rowstart,
                   const int2* __restrict__ csr,
                   const float* __restrict__ dinv,
                   const __half* __restrict__ feat,
                   const float* __restrict__ b2,
                   const float* __restrict__ gamma,
                   const float* __restrict__ beta,
                   void* __restrict__ outb, int n) {
    const int node = (blockIdx.x * blockDim.x + threadIdx.x) >> 5;
    const int lane = threadIdx.x & 31;
    if (node >= n) return;

    const uint2* fp = (const uint2*)feat;   // row = 32 uint2
    float dv = dinv[node];
    float4 acc = h4_to_f4(fp[node * 32 + lane]);
    acc.x *= dv; acc.y *= dv; acc.z *= dv; acc.w *= dv;

    const int beg = rowstart[node];
    const int end = rowstart[node + 1];

    int j = beg;
    for (; j + 3 < end; j += 4) {
        int2 e0 = csr[j], e1 = csr[j + 1], e2 = csr[j + 2], e3 = csr[j + 3];
        uint2 r0 = fp[e0.x * 32 + lane];
        uint2 r1 = fp[e1.x * 32 + lane];
        uint2 r2 = fp[e2.x * 32 + lane];
        uint2 r3 = fp[e3.x * 32 + lane];
        float4 v0 = h4_to_f4(r0), v1 = h4_to_f4(r1);
        float4 v2 = h4_to_f4(r2), v3 = h4_to_f4(r3);
        float n0 = __int_as_float(e0.y), n1 = __int_as_float(e1.y);
        float n2 = __int_as_float(e2.y), n3 = __int_as_float(e3.y);
        acc.x = fmaf(v0.x, n0, acc.x); acc.y = fmaf(v0.y, n0, acc.y);
        acc.z = fmaf(v0.z, n0, acc.z); acc.w = fmaf(v0.w, n0, acc.w);
        acc.x = fmaf(v1.x, n1, acc.x); acc.y = fmaf(v1.y, n1, acc.y);
        acc.z = fmaf(v1.z, n1, acc.z); acc.w = fmaf(v1.w, n1, acc.w);
        acc.x = fmaf(v2.x, n2, acc.x); acc.y = fmaf(v2.y, n2, acc.y);
        acc.z = fmaf(v2.z, n2, acc.z); acc.w = fmaf(v2.w, n2, acc.w);
        acc.x = fmaf(v3.x, n3, acc.x); acc.y = fmaf(v3.y, n3, acc.y);
        acc.z = fmaf(v3.z, n3, acc.z); acc.w = fmaf(v3.w, n3, acc.w);
    }
    for (; j < end; j++) {
        int2 e0 = csr[j];
        float4 v0 = h4_to_f4(fp[e0.x * 32 + lane]);
        float n0 = __int_as_float(e0.y);
        acc.x = fmaf(v0.x, n0, acc.x); acc.y = fmaf(v0.y, n0, acc.y);
        acc.z = fmaf(v0.z, n0, acc.z); acc.w = fmaf(v0.w, n0, acc.w);
    }

    acc.x *= dv; acc.y *= dv; acc.z *= dv; acc.w *= dv;

    if (DO_LN) {
        float4 bb = *(const float4*)(b2 + lane * 4);
        acc.x += bb.x; acc.y += bb.y; acc.z += bb.z; acc.w += bb.w;

        float s = acc.x + acc.y + acc.z + acc.w;
#pragma unroll
        for (int o = 16; o > 0; o >>= 1) s += __shfl_xor_sync(0xFFFFFFFFu, s, o);
        float mu = s * (1.0f / DIN);

        float dx = acc.x - mu, dy = acc.y - mu, dz = acc.z - mu, dw = acc.w - mu;
        float q = dx * dx + dy * dy + dz * dz + dw * dw;
#pragma unroll
        for (int o = 16; o > 0; o >>= 1) q += __shfl_xor_sync(0xFFFFFFFFu, q, o);
        float rstd = rsqrtf(q * (1.0f / DIN) + 1e-5f);

        float4 g  = *(const float4*)(gamma + lane * 4);
        float4 bt = *(const float4*)(beta + lane * 4);
        float4 o4;
        o4.x = dx * rstd * g.x + bt.x;
        o4.y = dy * rstd * g.y + bt.y;
        o4.z = dz * rstd * g.z + bt.z;
        o4.w = dw * rstd * g.w + bt.w;
        *(float4*)((float*)outb + (size_t)node * DIN + lane * 4) = o4;
    } else {
        __half2 h0 = __floats2half2_rn(acc.x, acc.y);
        __half2 h1 = __floats2half2_rn(acc.z, acc.w);
        uint2 pk = make_uint2(*(uint32_t*)&h0, *(uint32_t*)&h1);
        ((uint2*)outb)[node * 32 + lane] = pk;
    }
}

// ---------------- fused MLP: p = relu(A@W1^T + b1) @ W2^T --------------------
__device__ __forceinline__ void mma_f16(float c[4], const uint32_t a[4],
                                        const uint32_t b[2]) {
    asm volatile(
        "mma.sync.aligned.m16n8k16.row.col.f32.f16.f16.f32 "
        "{%0,%1,%2,%3}, {%4,%5,%6,%7}, {%8,%9}, {%0,%1,%2,%3};"
        : "+f"(c[0]), "+f"(c[1]), "+f"(c[2]), "+f"(c[3])
        : "r"(a[0]), "r"(a[1]), "r"(a[2]), "r"(a[3]), "r"(b[0]), "r"(b[1]));
}

#define AS_ST 68    // uints per row (64 data + 4 pad): 128-half rows
#define W2_ST 132   // uints per row (128 data + 4 pad): 256-half rows
#define SM_A  0
#define SM_W  (SM_A + 128 * AS_ST)
#define SM_H  (SM_W + 128 * W2_ST)
#define SM_TOTAL_U (SM_H + 128 * W2_ST)

__global__ __launch_bounds__(256, 1)
void fused_mlp_kernel(const __half* __restrict__ A,
                      const __half* __restrict__ W1,
                      const __half* __restrict__ W2,
                      const float* __restrict__ b1,
                      __half* __restrict__ P, int M) {
    extern __shared__ uint32_t sm[];
    uint32_t* A_s = sm + SM_A;
    uint32_t* W_s = sm + SM_W;
    uint32_t* H_s = sm + SM_H;

    const int tid  = threadIdx.x;
    const int lane = tid & 31;
    const int warp = tid >> 5;
    const int wm   = warp & 3;
    const int wn   = warp >> 2;
    const int gid  = lane >> 2;
    const int tig  = lane & 3;
    const int m0   = blockIdx.x * 128;

#pragma unroll
    for (int l = 0; l < 8; l++) {
        int idx = tid + l * 256;
        int row = idx >> 4;
        int q   = idx & 15;
        uint4 v = (m0 + row < M)
                ? *(const uint4*)(A + (size_t)(m0 + row) * DIN + q * 8)
                : make_uint4(0u, 0u, 0u, 0u);
        *(uint4*)&A_s[row * AS_ST + q * 4] = v;
    }

    for (int nh = 0; nh < 2; nh++) {
#pragma unroll
        for (int l = 0; l < 8; l++) {
            int idx = tid + l * 256;
            int row = idx >> 4;
            int q   = idx & 15;
            uint4 v = *(const uint4*)(W1 + (size_t)(nh * 128 + row) * DIN + q * 8);
            *(uint4*)&W_s[row * AS_ST + q * 4] = v;
        }
        __syncthreads();

        float acc[2][8][4];
#pragma unroll
        for (int i = 0; i < 2; i++)
#pragma unroll
            for (int j = 0; j < 8; j++)
#pragma unroll
                for (int q = 0; q < 4; q++) acc[i][j][q] = 0.f;

#pragma unroll
        for (int s = 0; s < 8; s++) {
            const int k2 = s * 8;
            uint32_t af[2][4];
#pragma unroll
            for (int mt = 0; mt < 2; mt++) {
                int rb = wm * 32 + mt * 16;
                af[mt][0] = A_s[(rb + gid) * AS_ST + k2 + tig];
                af[mt][1] = A_s[(rb + gid + 8) * AS_ST + k2 + tig];
                af[mt][2] = A_s[(rb + gid) * AS_ST + k2 + tig + 4];
                af[mt][3] = A_s[(rb + gid + 8) * AS_ST + k2 + tig + 4];
            }
            uint32_t bf[8][2];
#pragma unroll
            for (int ntl = 0; ntl < 8; ntl++) {
                int col = wn * 64 + ntl * 8 + gid;
                bf[ntl][0] = W_s[col * AS_ST + k2 + tig];
                bf[ntl][1] = W_s[col * AS_ST + k2 + tig + 4];
            }
#pragma unroll
            for (int mt = 0; mt < 2; mt++)
#pragma unroll
                for (int ntl = 0; ntl < 8; ntl++)
                    mma_f16(acc[mt][ntl], af[mt], bf[ntl]);
        }
        __syncthreads();

#pragma unroll
        for (int mt = 0; mt < 2; mt++) {
            int r0 = wm * 32 + mt * 16 + gid;
            int r1 = r0 + 8;
#pragma unroll
            for (int ntl = 0; ntl < 8; ntl++) {
                int colL = wn * 64 + ntl * 8 + tig * 2;
                int colG = nh * 128 + colL;
                float bx = b1[colG], by = b1[colG + 1];
                float2 v0 = make_float2(fmaxf(acc[mt][ntl][0] + bx, 0.f),
                                        fmaxf(acc[mt][ntl][1] + by, 0.f));
                float2 v1 = make_float2(fmaxf(acc[mt][ntl][2] + bx, 0.f),
                                        fmaxf(acc[mt][ntl][3] + by, 0.f));
                __half2 h0 = __floats2half2_rn(v0.x, v0.y);
                __half2 h1 = __floats2half2_rn(v1.x, v1.y);
                H_s[r0 * W2_ST + (colG >> 1)] = *(uint32_t*)&h0;
                H_s[r1 * W2_ST + (colG >> 1)] = *(uint32_t*)&h1;
            }
        }
    }

#pragma unroll
    for (int l = 0; l < 16; l++) {
        int idx = tid + l * 256;
        int row = idx >> 5;
        int q   = idx & 31;
        uint4 v = *(const uint4*)(W2 + (size_t)row * DH + q * 8);
        *(uint4*)&W_s[row * W2_ST + q * 4] = v;
    }
    __syncthreads();

    float acc2[2][8][4];
#pragma unroll
    for (int i = 0; i < 2; i++)
#pragma unroll
        for (int j = 0; j < 8; j++)
#pragma unroll
            for (int q = 0; q < 4; q++) acc2[i][j][q] = 0.f;

#pragma unroll
    for (int s = 0; s < 16; s++) {
        const int k2 = s * 8;
        uint32_t af[2][4];
#pragma unroll
        for (int mt = 0; mt < 2; mt++) {
            int rb = wm * 32 + mt * 16;
            af[mt][0] = H_s[(rb + gid) * W2_ST + k2 + tig];
            af[mt][1] = H_s[(rb + gid + 8) * W2_ST + k2 + tig];
            af[mt][2] = H_s[(rb + gid) * W2_ST + k2 + tig + 4];
            af[mt][3] = H_s[(rb + gid + 8) * W2_ST + k2 + tig + 4];
        }
        uint32_t bf[8][2];
#pragma unroll
        for (int ntl = 0; ntl < 8; ntl++) {
            int col = wn * 64 + ntl * 8 + gid;
            bf[ntl][0] = W_s[col * W2_ST + k2 + tig];
            bf[ntl][1] = W_s[col * W2_ST + k2 + tig + 4];
        }
#pragma unroll
        for (int mt = 0; mt < 2; mt++)
#pragma unroll
            for (int ntl = 0; ntl < 8; ntl++)
                mma_f16(acc2[mt][ntl], af[mt], bf[ntl]);
    }

#pragma unroll
    for (int mt = 0; mt < 2; mt++) {
        int row0 = m0 + wm * 32 + mt * 16 + gid;
        int row1 = row0 + 8;
#pragma unroll
        for (int ntl = 0; ntl < 8; ntl++) {
            int col = wn * 64 + ntl * 8 + tig * 2;
            __half2 h0 = __floats2half2_rn(acc2[mt][ntl][0], acc2[mt][ntl][1]);
            __half2 h1 = __floats2half2_rn(acc2[mt][ntl][2], acc2[mt][ntl][3]);
            if (row0 < M) *(__half2*)(P + (size_t)row0 * DIN + col) = h0;
            if (row1 < M) *(__half2*)(P + (size_t)row1 * DIN + col) = h1;
        }
    }
}

// -----------------------------------------------------------------------------
extern "C" void kernel_launch(void* const* d_in, const int* in_sizes, int n_in,
                              void* d_out, int out_size) {
    const float* x     = (const float*)d_in[0];
    const void*  ei    = d_in[1];
    const float* ew    = (const float*)d_in[2];
    const float* W1    = (const float*)d_in[3];
    const float* b1    = (const float*)d_in[4];
    const float* W2    = (const float*)d_in[5];
    const float* b2    = (const float*)d_in[6];
    const float* gamma = (const float*)d_in[7];
    const float* beta  = (const float*)d_in[8];
    float*       out   = (float*)d_out;

    float *dinv;
    __half *xh, *a1h, *ph, *w1h, *w2h;
    int *cnt, *rowstart;
    uint2 *stage;
    int2 *csr;
    cudaGetSymbolAddress((void**)&dinv,     g_dinv);
    cudaGetSymbolAddress((void**)&xh,       g_xh);
    cudaGetSymbolAddress((void**)&a1h,      g_a1h);
    cudaGetSymbolAddress((void**)&ph,       g_ph);
    cudaGetSymbolAddress((void**)&w1h,      g_w1h);
    cudaGetSymbolAddress((void**)&w2h,      g_w2h);
    cudaGetSymbolAddress((void**)&cnt,      g_count);
    cudaGetSymbolAddress((void**)&rowstart, g_rowstart);
    cudaGetSymbolAddress((void**)&stage,    g_stage);
    cudaGetSymbolAddress((void**)&csr,      g_csr);

    const int n = NN, e = EE;
    const int smem_bytes = SM_TOTAL_U * 4;

    static cudaStream_t s1 = nullptr;
    static cudaEvent_t evFork = nullptr, evConv = nullptr;
    static bool init_done = false;
    if (!init_done) {
        cudaFuncSetAttribute(fused_mlp_kernel,
                             cudaFuncAttributeMaxDynamicSharedMemorySize,
                             smem_bytes);
        cudaStreamCreateWithFlags(&s1, cudaStreamNonBlocking);
        cudaEventCreateWithFlags(&evFork, cudaEventDisableTiming);
        cudaEventCreateWithFlags(&evConv, cudaEventDisableTiming);
        init_done = true;
    }

    // ---- fork: fp16 conversions on side stream (parallel graph branch) ----
    cudaEventRecord(evFork, 0);
    cudaStreamWaitEvent(s1, evFork, 0);
    conv_kernel<<<512, 256, 0, s1>>>(x, W1, W2);
    cudaEventRecord(evConv, s1);

    // ---- edge chain on main stream ----
    zero_kernel<<<256, 256>>>((const int*)ei, dinv, cnt);
    convert_deg_kernel<<<(e / 4 + 255) / 256, 256>>>(ei, ew, dinv, cnt, stage, e);
    scan_lookback_kernel<<<NBLK, 256>>>(cnt, dinv, rowstart, n);
    csr_fill_kernel<<<(e / 4 + 255) / 256, 256>>>(stage, ew, dinv, rowstart, csr, e);

    // ---- join: gather1 needs xh (side branch) + csr (main branch) ----
    cudaStreamWaitEvent(0, evConv, 0);
    gather_kernel<0><<<(n * 32 + 255) / 256, 256>>>(rowstart, csr, dinv, xh,
                                                    nullptr, nullptr, nullptr,
                                                    a1h, n);

    fused_mlp_kernel<<<(n + 127) / 128, 256, smem_bytes>>>(a1h, w1h, w2h, b1,
                                                           ph, n);

    gather_kernel<1><<<(n * 32 + 255) / 256, 256>>>(rowstart, csr, dinv, ph,
                                                    b2, gamma, beta, out, n);
}